// round 11
// baseline (speedup 1.0000x reference)
#include <cuda_runtime.h>
#include <cstdint>

#define SEQ  4096
#define NQ   64
#define DH   128
#define BMAX 16
#define SCALE 0.088388347648318447f
#define P 136
#define TILE_U (32*P)
#define NCH (SEQ/32)
// smem: Kring[3] Vring[3] W[2] (8 tiles) + a_s
#define DSMEM (8*TILE_U*4 + SEQ*4)

__device__ float g_Kr[(size_t)BMAX*SEQ*DH];
__device__ float g_Vr[(size_t)BMAX*SEQ*DH];

__device__ __forceinline__ float tf32r(float x) {
    uint32_t r;
    asm("cvt.rna.tf32.f32 %0, %1;" : "=r"(r) : "f"(x));
    return __uint_as_float(r);
}
__device__ __forceinline__ void mma_tf32(float* d, const uint32_t* a,
                                         uint32_t b0, uint32_t b1) {
    asm volatile(
        "mma.sync.aligned.m16n8k8.row.col.f32.tf32.tf32.f32 "
        "{%0,%1,%2,%3}, {%4,%5,%6,%7}, {%8,%9}, {%0,%1,%2,%3};"
        : "+f"(d[0]), "+f"(d[1]), "+f"(d[2]), "+f"(d[3])
        : "r"(a[0]), "r"(a[1]), "r"(a[2]), "r"(a[3]), "r"(b0), "r"(b1));
}
__device__ __forceinline__ void cpa16(uint32_t dst, const void* src) {
    asm volatile("cp.async.ca.shared.global [%0], [%1], 16;" :: "r"(dst), "l"(src));
}
#define CPA_COMMIT() asm volatile("cp.async.commit_group;" ::: "memory")
#define CPA_WAIT(n)  asm volatile("cp.async.wait_group %0;" :: "n"(n) : "memory")

__global__ void prep_kernel(const float* __restrict__ K, const float* __restrict__ V,
                            int total4) {
    int i = blockIdx.x * blockDim.x + threadIdx.x;
    if (i >= total4) return;
    float4 k = ((const float4*)K)[i];
    float4 v = ((const float4*)V)[i];
    ((float4*)g_Kr)[i] = make_float4(tf32r(k.x), tf32r(k.y), tf32r(k.z), tf32r(k.w));
    ((float4*)g_Vr)[i] = make_float4(tf32r(v.x), tf32r(v.y), tf32r(v.z), tf32r(v.w));
}

__device__ __forceinline__ void mma_phase(const uint32_t* Wc, const uint32_t* Kc,
                                          float (*acc)[4][4], int v0, int k0,
                                          int g, int ti) {
    #pragma unroll
    for (int s = 0; s < 4; s++) {
        const uint32_t* Wr0 = Wc + (s*8 + ti)*P;
        const uint32_t* Wr4 = Wr0 + 4*P;
        uint32_t af[2][4];
        #pragma unroll
        for (int mi = 0; mi < 2; mi++) {
            int cb = v0 + mi*16 + g;
            af[mi][0] = Wr0[cb];   af[mi][1] = Wr0[cb+8];
            af[mi][2] = Wr4[cb];   af[mi][3] = Wr4[cb+8];
        }
        const uint32_t* Kr0 = Kc + (s*8 + ti)*P;
        const uint32_t* Kr4 = Kr0 + 4*P;
        #pragma unroll
        for (int nj = 0; nj < 4; nj++) {
            int cb = k0 + nj*8 + g;
            uint32_t b0 = Kr0[cb], b1 = Kr4[cb];
            mma_tf32(acc[0][nj], af[0], b0, b1);
            mma_tf32(acc[1][nj], af[1], b0, b1);
        }
    }
}

__global__ __launch_bounds__(512, 1)
void jac_tc(const float* __restrict__ Q, const float* __restrict__ K,
            float* __restrict__ out)
{
    extern __shared__ uint32_t sm[];
    uint32_t* Kring = sm;                 // 3 tiles
    uint32_t* Vring = sm + 3*TILE_U;      // 3 tiles
    uint32_t* Wbuf  = sm + 6*TILE_U;      // 2 tiles
    float*    a_s   = (float*)(sm + 8*TILE_U);
    __shared__ float q_sm[DH], o_sm[DH], w_sm[DH], red_sm[16];

    const int tid = threadIdx.x, lane = tid & 31, wid = tid >> 5;
    const int q = blockIdx.x, b = blockIdx.y;
    const float* __restrict__ Kb = K + (size_t)b * SEQ * DH;

    if (tid < 32) ((float4*)q_sm)[tid] =
        ((const float4*)(Q + ((size_t)b*NQ + q)*DH))[tid];
    __syncthreads();

    // ---- Phase 1: scores ----
    float4 qf = ((const float4*)q_sm)[lane];
    float lmax = -1e30f;
    for (int n = wid; n < SEQ; n += 16) {
        float4 kf = ((const float4*)(Kb + (size_t)n*DH))[lane];
        float dp = qf.x*kf.x + qf.y*kf.y + qf.z*kf.z + qf.w*kf.w;
        dp += __shfl_xor_sync(~0u, dp, 16); dp += __shfl_xor_sync(~0u, dp, 8);
        dp += __shfl_xor_sync(~0u, dp, 4);  dp += __shfl_xor_sync(~0u, dp, 2);
        dp += __shfl_xor_sync(~0u, dp, 1);
        dp *= SCALE;
        if (lane == 0) a_s[n] = dp;
        lmax = fmaxf(lmax, dp);
    }
    if (lane == 0) red_sm[wid] = lmax;
    __syncthreads();
    float gmax = red_sm[0];
    #pragma unroll
    for (int i = 1; i < 16; i++) gmax = fmaxf(gmax, red_sm[i]);
    __syncthreads();

    // ---- Phase 2: softmax ----
    float lsum = 0.f;
    for (int n = tid; n < SEQ; n += 512) {
        float e = __expf(a_s[n] - gmax); a_s[n] = e; lsum += e;
    }
    lsum += __shfl_xor_sync(~0u, lsum, 16); lsum += __shfl_xor_sync(~0u, lsum, 8);
    lsum += __shfl_xor_sync(~0u, lsum, 4);  lsum += __shfl_xor_sync(~0u, lsum, 2);
    lsum += __shfl_xor_sync(~0u, lsum, 1);
    if (lane == 0) red_sm[wid] = lsum;
    __syncthreads();
    float gsum = 0.f;
    #pragma unroll
    for (int i = 0; i < 16; i++) gsum += red_sm[i];
    const float inv = 1.0f / gsum;
    for (int n = tid; n < SEQ; n += 512) a_s[n] *= inv;
    __syncthreads();

    // ---- Phase 3: cp.async 3-stage pipelined tf32 mma ----
    const float* Krb = g_Kr + (size_t)b*SEQ*DH;
    const float* Vrb = g_Vr + (size_t)b*SEQ*DH;
    const int sn = tid >> 4, scb = (tid & 15) * 8;
    const int g = lane >> 2, ti = lane & 3;
    const int v0 = (wid & 3) * 32, k0 = (wid >> 2) * 32;
    const uint32_t soff = (sn*P + scb) * 4;   // byte offset of this thread's slice
    const uint32_t kring_sa = (uint32_t)__cvta_generic_to_shared(Kring);
    const uint32_t vring_sa = (uint32_t)__cvta_generic_to_shared(Vring);

    float pov[8], pwv[8];
    #pragma unroll
    for (int j = 0; j < 8; j++) { pov[j] = 0.f; pwv[j] = 0.f; }
    float acc[2][4][4];
    #pragma unroll
    for (int mi = 0; mi < 2; mi++)
        #pragma unroll
        for (int nj = 0; nj < 4; nj++)
            #pragma unroll
            for (int e = 0; e < 4; e++) acc[mi][nj][e] = 0.f;

    // issue K+V tile loads for chunk ch into ring slot ch%3
    #define ISSUE(ch_) do {                                             \
        int _c = (ch_) < NCH ? (ch_) : 0;                               \
        uint32_t _slot = ((uint32_t)(ch_)) % 3u;                        \
        const float* _ks = Krb + (size_t)(_c*32 + sn)*DH + scb;         \
        const float* _vs = Vrb + (size_t)(_c*32 + sn)*DH + scb;         \
        uint32_t _kd = kring_sa + _slot*(TILE_U*4) + soff;              \
        uint32_t _vd = vring_sa + _slot*(TILE_U*4) + soff;              \
        cpa16(_kd, _ks); cpa16(_kd + 16, _ks + 4);                      \
        cpa16(_vd, _vs); cpa16(_vd + 16, _vs + 4);                      \
        CPA_COMMIT();                                                   \
    } while (0)

    ISSUE(0);
    ISSUE(1);

    for (int ch = 0; ch < NCH; ch++) {
        const int slot = ch % 3, wsel = ch & 1;
        CPA_WAIT(1);                 // slot `ch` data arrived (thread-local)
        __syncthreads();             // CTA-wide visibility

        // transform: W[wsel] = a * Vslot ; partials
        {
            const uint32_t* Ks = Kring + slot*TILE_U + sn*P + scb;
            const uint32_t* Vs = Vring + slot*TILE_U + sn*P + scb;
            uint32_t* wd = Wbuf + wsel*TILE_U + sn*P + scb;
            float av = a_s[ch*32 + sn];
            uint4 ku0 = *(const uint4*)Ks, ku1 = *(const uint4*)(Ks + 4);
            uint4 vu0 = *(const uint4*)Vs, vu1 = *(const uint4*)(Vs + 4);
            float kx[8] = {__uint_as_float(ku0.x), __uint_as_float(ku0.y),
                           __uint_as_float(ku0.z), __uint_as_float(ku0.w),
                           __uint_as_float(ku1.x), __uint_as_float(ku1.y),
                           __uint_as_float(ku1.z), __uint_as_float(ku1.w)};
            float vx[8] = {__uint_as_float(vu0.x), __uint_as_float(vu0.y),
                           __uint_as_float(vu0.z), __uint_as_float(vu0.w),
                           __uint_as_float(vu1.x), __uint_as_float(vu1.y),
                           __uint_as_float(vu1.z), __uint_as_float(vu1.w)};
            uint32_t wv[8];
            #pragma unroll
            for (int j = 0; j < 8; j++) {
                pwv[j] += av * kx[j];
                float w = av * vx[j];
                pov[j] += w;
                wv[j] = __float_as_uint(w) + 0x1000u;   // RN into tf32 bits
            }
            *(uint4*)wd       = make_uint4(wv[0], wv[1], wv[2], wv[3]);
            *(uint4*)(wd + 4) = make_uint4(wv[4], wv[5], wv[6], wv[7]);
        }
        __syncthreads();             // W ready; prev slot fully consumed
        ISSUE(ch + 2);               // refill slot (ch+2)%3 (now free)
        mma_phase(Wbuf + wsel*TILE_U, Kring + slot*TILE_U, acc, v0, k0, g, ti);
    }
    CPA_WAIT(0);                     // drain tail dummies before smem reuse
    __syncthreads();

    // ---- reduce o/w partials (reuse ring smem) ----
    float* opart = (float*)sm;
    float* wpart = (float*)(sm + TILE_U);
    #pragma unroll
    for (int j = 0; j < 8; j++) {
        opart[sn*DH + scb + j] = pov[j];
        wpart[sn*DH + scb + j] = pwv[j];
    }
    __syncthreads();
    if (tid < DH) {
        float s = 0.f;
        #pragma unroll
        for (int n = 0; n < 32; n++) s += opart[n*DH + tid];
        o_sm[tid] = s;
    } else if (tid < 2*DH) {
        int t = tid - DH;
        float s = 0.f;
        #pragma unroll
        for (int n = 0; n < 32; n++) s += wpart[n*DH + t];
        w_sm[t] = s;
    }
    __syncthreads();

    // ---- epilogue ----
    float* ob = out + ((size_t)b*NQ + q) * DH * DH;
    #pragma unroll
    for (int mi = 0; mi < 2; mi++) {
        int vr = v0 + mi*16 + g;
        float ov1 = o_sm[vr], ov2 = o_sm[vr + 8];
        #pragma unroll
        for (int nj = 0; nj < 4; nj++) {
            int kc = k0 + nj*8 + ti*2;
            float w1 = w_sm[kc], w2 = w_sm[kc+1];
            float2 r1 = make_float2(SCALE*(acc[mi][nj][0] - ov1*w1),
                                    SCALE*(acc[mi][nj][1] - ov1*w2));
            float2 r2 = make_float2(SCALE*(acc[mi][nj][2] - ov2*w1),
                                    SCALE*(acc[mi][nj][3] - ov2*w2));
            *(float2*)(ob + (size_t)vr*DH + kc)     = r1;
            *(float2*)(ob + (size_t)(vr+8)*DH + kc) = r2;
        }
    }
}

extern "C" void kernel_launch(void* const* d_in, const int* in_sizes, int n_in,
                              void* d_out, int out_size) {
    const float* Q = (const float*)d_in[0];
    const float* K = (const float*)d_in[1];
    const float* V = (const float*)d_in[2];
    float* out = (float*)d_out;
    int batch = in_sizes[1] / (SEQ * DH);
    int total4 = batch * SEQ * DH / 4;
    prep_kernel<<<(total4 + 255)/256, 256>>>(K, V, total4);
    cudaFuncSetAttribute(jac_tc, cudaFuncAttributeMaxDynamicSharedMemorySize, DSMEM);
    jac_tc<<<dim3(NQ, batch), 512, DSMEM>>>(Q, K, out);
}